// round 16
// baseline (speedup 1.0000x reference)
#include <cuda_runtime.h>
#include <cuda_fp16.h>
#include <cstdint>
#include <math.h>

#define BB   16
#define NPTS 4096
#define MPTS 1024
#define CH   256     // C1 = C2 = H1 = H2
#define LDW1 512     // w1 row stride (Cin)

// ---------------------------------------------------------------------------
// Scratch (static device globals)
// ---------------------------------------------------------------------------
__device__ int     g_idx[BB * NPTS * 3];
__device__ float   g_wts[BB * NPTS * 3];
__device__ __half  g_Gh[BB * MPTS * CH];       // [b][m][o] fp16
__device__ __half  g_Hf[BB * NPTS * CH];       // [b][n][k] fp16
__device__ __half  g_X1f[BB * NPTS * CH];      // feat1^T  [b][n][k] fp16
__device__ __half  g_X2f[BB * MPTS * CH];      // feat2^T  [b][m][k] fp16
__device__ __half  g_W1af[CH * CH];            // fp16 weights
__device__ __half  g_W1bf[CH * CH];
__device__ __half  g_W2f[CH * CH];

// ---------------------------------------------------------------------------
// PTX helpers (sm_80-baseline features only — valid on plain sm_100)
// ---------------------------------------------------------------------------
__device__ __forceinline__ uint32_t smem_u32(const void* p) {
    uint32_t a;
    asm("{ .reg .u64 t; cvta.to.shared.u64 t, %1; cvt.u32.u64 %0, t; }"
        : "=r"(a) : "l"(p));
    return a;
}
__device__ __forceinline__ void cp_async16(uint32_t saddr, const void* g) {
    asm volatile("cp.async.cg.shared.global [%0], [%1], 16;"
                 :: "r"(saddr), "l"(g) : "memory");
}
__device__ __forceinline__ void cp_commit() {
    asm volatile("cp.async.commit_group;" ::: "memory");
}
__device__ __forceinline__ void cp_wait1() {
    asm volatile("cp.async.wait_group 1;" ::: "memory");
}
__device__ __forceinline__ void ldm_x4(uint32_t* r, uint32_t addr) {
    asm volatile("ldmatrix.sync.aligned.m8n8.x4.shared.b16 {%0,%1,%2,%3}, [%4];"
                 : "=r"(r[0]), "=r"(r[1]), "=r"(r[2]), "=r"(r[3]) : "r"(addr));
}
__device__ __forceinline__ void mma_f16(float* d, const uint32_t* a, const uint32_t* b) {
    asm volatile(
        "mma.sync.aligned.m16n8k16.row.col.f32.f16.f16.f32 "
        "{%0,%1,%2,%3}, {%4,%5,%6,%7}, {%8,%9}, {%0,%1,%2,%3};"
        : "+f"(d[0]), "+f"(d[1]), "+f"(d[2]), "+f"(d[3])
        : "r"(a[0]), "r"(a[1]), "r"(a[2]), "r"(a[3]), "r"(b[0]), "r"(b[1]));
}

// ---------------------------------------------------------------------------
// Kernel A: merged prep — kNN + 3 weight fp16 converts + 2 feature transposes.
// ---------------------------------------------------------------------------
#define PREP_KNN_BLKS    256
#define PREP_W_BLKS      768
#define PREP_T2_BLKS     2048            // (MPTS/32) * (CH/64) * BB
#define PREP_T1_BLKS     8192            // (NPTS/32) * (CH/64) * BB
#define PREP_TOTAL       (PREP_KNN_BLKS + PREP_W_BLKS + PREP_T2_BLKS + PREP_T1_BLKS)

__device__ __forceinline__ void do_transpose_f16(
    const float* __restrict__ Xb, int nn, int n0, int k0,
    __half* __restrict__ T, float (*s)[33], int t)
{
    const int tx = t & 31, ty = t >> 5;
    #pragma unroll
    for (int j = 0; j < 8; ++j) {
        const int kl = ty + j * 8;                 // 0..63
        s[kl][tx] = Xb[(size_t)(k0 + kl) * nn + n0 + tx];
    }
    __syncthreads();
    const int nl = t >> 3;                         // 0..31
    const int kp = (t & 7) * 8;                    // 0..56
    __half h[8];
    #pragma unroll
    for (int q = 0; q < 8; ++q)
        h[q] = __float2half(s[kp + q][nl]);
    *(uint4*)&T[(size_t)(n0 + nl) * CH + k0 + kp] = *(uint4*)h;
}

__global__ __launch_bounds__(256)
void prep_kernel(const float* __restrict__ xyz1,  const float* __restrict__ xyz2,
                 const float* __restrict__ feat1, const float* __restrict__ feat2,
                 const float* __restrict__ w1,    const float* __restrict__ w2)
{
    __shared__ char smbuf[MPTS * 16];  // 16KB: float4[MPTS] / float[64][33]
    const int bid = blockIdx.x;
    const int t   = threadIdx.x;

    if (bid < PREP_KNN_BLKS) {
        float4* s4 = (float4*)smbuf;
        const int b = bid >> 4;
        const int g = bid & 15;

        for (int m = t; m < MPTS; m += 256) {
            const float* q = xyz2 + ((size_t)b * MPTS + m) * 3;
            const float x = q[0], y = q[1], z = q[2];
            s4[m] = make_float4(x, y, z, x * x + y * y + z * z);
        }
        __syncthreads();

        const int n = g * 256 + t;
        const float* p = xyz1 + ((size_t)b * NPTS + n) * 3;
        const float px = p[0], py = p[1], pz = p[2];
        const float qx2 = -2.0f * px, qy2 = -2.0f * py, qz2 = -2.0f * pz;
        const float qsq = px * px + py * py + pz * pz;

        float d0 = 3.4e38f, d1 = 3.4e38f, d2 = 3.4e38f;
        int   i0 = 0, i1 = 0, i2 = 0;

        #pragma unroll 4
        for (int m = 0; m < MPTS; ++m) {
            const float4 v = s4[m];
            float d = v.w;
            d = fmaf(qx2, v.x, d);
            d = fmaf(qy2, v.y, d);
            d = fmaf(qz2, v.z, d);
            if (d < d2) {
                if (d < d0)      { d2 = d1; i2 = i1; d1 = d0; i1 = i0; d0 = d; i0 = m; }
                else if (d < d1) { d2 = d1; i2 = i1; d1 = d;  i1 = m; }
                else             { d2 = d;  i2 = m; }
            }
        }

        d0 += qsq; d1 += qsq; d2 += qsq;
        const float wa = 1.0f / (d0 + 1e-8f);
        const float wb = 1.0f / (d1 + 1e-8f);
        const float wc = 1.0f / (d2 + 1e-8f);
        const float ws = 1.0f / (wa + wb + wc);

        const size_t o = ((size_t)b * NPTS + n) * 3;
        g_idx[o + 0] = i0; g_idx[o + 1] = i1; g_idx[o + 2] = i2;
        g_wts[o + 0] = wa * ws; g_wts[o + 1] = wb * ws; g_wts[o + 2] = wc * ws;
        return;
    }

    float (*s)[33] = (float (*)[33])smbuf;

    if (bid < PREP_KNN_BLKS + PREP_W_BLKS) {
        const int local = bid - PREP_KNN_BLKS;
        const int which = local >> 8;
        const int idx   = (local & 255) * 256 + t;
        const int o = idx >> 8, k = idx & 255;
        if (which == 0)      g_W1af[idx] = __float2half(w1[(size_t)o * LDW1 + k]);
        else if (which == 1) g_W1bf[idx] = __float2half(w1[(size_t)o * LDW1 + 256 + k]);
        else                 g_W2f[idx]  = __float2half(w2[(size_t)o * CH + k]);
    } else if (bid < PREP_KNN_BLKS + PREP_W_BLKS + PREP_T2_BLKS) {
        const int local = bid - PREP_KNN_BLKS - PREP_W_BLKS;
        const int n0 = (local & 31) * 32;
        const int k0 = ((local >> 5) & 3) * 64;
        const int b  = local >> 7;
        do_transpose_f16(feat2 + (size_t)b * CH * MPTS, MPTS, n0, k0,
                         g_X2f + (size_t)b * MPTS * CH, s, t);
    } else {
        const int local = bid - PREP_KNN_BLKS - PREP_W_BLKS - PREP_T2_BLKS;
        const int n0 = (local & 127) * 32;
        const int k0 = ((local >> 7) & 3) * 64;
        const int b  = local >> 9;
        do_transpose_f16(feat1 + (size_t)b * CH * NPTS, NPTS, n0, k0,
                         g_X1f + (size_t)b * NPTS * CH, s, t);
    }
}

// ---------------------------------------------------------------------------
// Tensor-core GEMM, plain fp16 x fp16, single mma term. KC=64, SW128 swizzle.
//   2-stage double buffer -> 68KB smem/CTA -> 3 CTAs/SM (24 warps).
//   MODE 0: fp16 staged store -> g_Gh      (G GEMM)
//   MODE 1: BN+ReLU fp32 store -> Out      (GEMM2)
//   MODE 2: interp-add + BN + ReLU -> fp16 H   (F GEMM)
// ---------------------------------------------------------------------------
#define KTOT    256
#define KC      64
#define NCHUNK  (KTOT / KC)              // 4
#define ARR_B   (128 * 128)              // 16384 (128 rows x 64 fp16 = 128B)
#define STAGE_B (2 * ARR_B)              // 32768
#define NSTAGE  2
#define SMEM_GEMM 69632                  // >= max(2*STAGE_B=65536, S=67584)
#define SPITCH  132

__device__ __forceinline__ uint32_t swz(int row, int ch) {
    return (uint32_t)(row * 128 + ((ch ^ (row & 7)) << 4));
}

template<int MODE>
__global__ __launch_bounds__(256, 3)
void mma_gemm(const __half* __restrict__ A, size_t aBS, int aPerB,
              const __half* __restrict__ B, size_t bBS, int bPerB,
              float* __restrict__ Out, size_t oBS, int outLd,
              const float* __restrict__ gamma, const float* __restrict__ beta)
{
    extern __shared__ char sm[];
    const uint32_t sb = smem_u32(sm);

    const int tid  = threadIdx.x;
    const int warp = tid >> 5;
    const int lane = tid & 31;
    const int wm   = warp & 3;
    const int wn   = warp >> 2;
    const int bz   = blockIdx.z;

    const __half* srcs[2] = {
        A + (aPerB ? bz * aBS : 0) + (size_t)(blockIdx.y * 128) * KTOT,
        B + (bPerB ? bz * bBS : 0) + (size_t)(blockIdx.x * 128) * KTOT };

    auto load_stage = [&](int c) {
        const int k0 = c * KC;
        const uint32_t stage = sb + (c & 1) * STAGE_B;
        #pragma unroll
        for (int i = 0; i < 8; ++i) {
            const int id   = tid + i * 256;
            const int arr  = id >> 10;
            const int id10 = id & 1023;
            const int row  = id10 >> 3;
            const int ch   = id10 & 7;
            cp_async16(stage + arr * ARR_B + swz(row, ch),
                       srcs[arr] + (size_t)row * KTOT + k0 + ch * 8);
        }
        cp_commit();
    };

    float acc[2][8][4];
    #pragma unroll
    for (int a = 0; a < 2; ++a)
        #pragma unroll
        for (int b = 0; b < 8; ++b)
            #pragma unroll
            for (int d = 0; d < 4; ++d) acc[a][b][d] = 0.0f;

    load_stage(0);

    for (int c = 0; c < NCHUNK; ++c) {
        if (c + 1 < NCHUNK) load_stage(c + 1);
        else                cp_commit();
        cp_wait1();                      // stage c complete; c+1 in flight
        __syncthreads();

        const uint32_t stage = sb + (c & 1) * STAGE_B;
        const uint32_t aB = stage;
        const uint32_t bB = stage + ARR_B;

        #pragma unroll
        for (int s = 0; s < 4; ++s) {
            const int arow  = wm * 32 + (lane & 15);
            const int achnk = s * 2 + ((lane >> 4) & 1);
            const int brow  = wn * 64 + ((lane >> 4) << 3) + (lane & 7);
            const int bchnk = s * 2 + ((lane >> 3) & 1);

            uint32_t av[2][4];
            ldm_x4(av[0], aB + swz(arow,      achnk));
            ldm_x4(av[1], aB + swz(arow + 16, achnk));
            #pragma unroll
            for (int nt = 0; nt < 4; ++nt) {
                uint32_t bv[4];
                ldm_x4(bv, bB + swz(brow + nt * 16, bchnk));
                mma_f16(acc[0][2*nt],   av[0], bv);
                mma_f16(acc[1][2*nt],   av[1], bv);
                mma_f16(acc[0][2*nt+1], av[0], bv + 2);
                mma_f16(acc[1][2*nt+1], av[1], bv + 2);
            }
        }
        __syncthreads();                 // buffer c&1 free before c+2 loads it
    }

    const float inv = 1.0f / sqrtf(1.0f + 1e-5f);

    if (MODE == 2) {
        // gather interp (fp16 G, high MLP) -> S, add acc, BN+ReLU, fp16 store
        float* S = (float*)sm;
        const int n0 = blockIdx.x * 128;
        const int o0 = blockIdx.y * 128;
        const __half* Gb = g_Gh + (size_t)bz * MPTS * CH;

        for (int j = 0; j < 16; ++j) {
            const int nl = warp * 16 + j;
            const size_t pb = (size_t)bz * NPTS + n0 + nl;
            const int   i0 = g_idx[pb * 3 + 0];
            const int   i1 = g_idx[pb * 3 + 1];
            const int   i2 = g_idx[pb * 3 + 2];
            const float w0 = g_wts[pb * 3 + 0];
            const float w1 = g_wts[pb * 3 + 1];
            const float w2 = g_wts[pb * 3 + 2];
            const __half2* gr0 = (const __half2*)(Gb + (size_t)i0 * CH + o0 + 4 * lane);
            const __half2* gr1 = (const __half2*)(Gb + (size_t)i1 * CH + o0 + 4 * lane);
            const __half2* gr2 = (const __half2*)(Gb + (size_t)i2 * CH + o0 + 4 * lane);
            const float2 a0 = __half22float2(gr0[0]), a1 = __half22float2(gr0[1]);
            const float2 b0 = __half22float2(gr1[0]), b1 = __half22float2(gr1[1]);
            const float2 c0 = __half22float2(gr2[0]), c1 = __half22float2(gr2[1]);
            float4 v;
            v.x = w0 * a0.x + w1 * b0.x + w2 * c0.x;
            v.y = w0 * a0.y + w1 * b0.y + w2 * c0.y;
            v.z = w0 * a1.x + w1 * b1.x + w2 * c1.x;
            v.w = w0 * a1.y + w1 * b1.y + w2 * c1.y;
            *(float4*)&S[nl * SPITCH + 4 * lane] = v;
        }
        __syncthreads();

        #pragma unroll
        for (int mi = 0; mi < 2; ++mi) {
            const int ol = wm * 32 + mi * 16 + (lane >> 2);
            #pragma unroll
            for (int nt = 0; nt < 8; ++nt) {
                const int cl = wn * 64 + nt * 8 + (lane & 3) * 2;
                S[cl * SPITCH + ol]           += acc[mi][nt][0];
                S[(cl + 1) * SPITCH + ol]     += acc[mi][nt][1];
                S[cl * SPITCH + ol + 8]       += acc[mi][nt][2];
                S[(cl + 1) * SPITCH + ol + 8] += acc[mi][nt][3];
            }
        }
        __syncthreads();

        const float4 gm = *(const float4*)&gamma[o0 + 4 * lane];
        const float4 bt = *(const float4*)&beta[o0 + 4 * lane];
        for (int j = 0; j < 16; ++j) {
            const int nl = warp * 16 + j;
            float4 v = *(float4*)&S[nl * SPITCH + 4 * lane];
            v.x = fmaxf(fmaf(v.x, gm.x * inv, bt.x), 0.0f);
            v.y = fmaxf(fmaf(v.y, gm.y * inv, bt.y), 0.0f);
            v.z = fmaxf(fmaf(v.z, gm.z * inv, bt.z), 0.0f);
            v.w = fmaxf(fmaf(v.w, gm.w * inv, bt.w), 0.0f);
            const size_t hb = ((size_t)bz * NPTS + n0 + nl) * CH + o0 + 4 * lane;
            *(__half2*)&g_Hf[hb]     = __floats2half2_rn(v.x, v.y);
            *(__half2*)&g_Hf[hb + 2] = __floats2half2_rn(v.z, v.w);
        }
        return;
    }

    if (MODE == 0) {
        // stage acc -> S, then coalesced fp16 row stores to g_Gh[m][o]
        float* S = (float*)sm;
        #pragma unroll
        for (int mi = 0; mi < 2; ++mi) {
            const int ol = wm * 32 + mi * 16 + (lane >> 2);
            #pragma unroll
            for (int nt = 0; nt < 8; ++nt) {
                const int cl = wn * 64 + nt * 8 + (lane & 3) * 2;
                S[cl * SPITCH + ol]           = acc[mi][nt][0];
                S[(cl + 1) * SPITCH + ol]     = acc[mi][nt][1];
                S[cl * SPITCH + ol + 8]       = acc[mi][nt][2];
                S[(cl + 1) * SPITCH + ol + 8] = acc[mi][nt][3];
            }
        }
        __syncthreads();

        __half* Gh = g_Gh + (size_t)bz * MPTS * CH;
        const int m0 = blockIdx.x * 128;
        const int o0 = blockIdx.y * 128;
        for (int j = 0; j < 16; ++j) {
            const int r = warp * 16 + j;
            float4 v = *(float4*)&S[r * SPITCH + 4 * lane];
            __half2 h0 = __floats2half2_rn(v.x, v.y);
            __half2 h1 = __floats2half2_rn(v.z, v.w);
            *(__half2*)&Gh[(size_t)(m0 + r) * CH + o0 + 4 * lane]     = h0;
            *(__half2*)&Gh[(size_t)(m0 + r) * CH + o0 + 4 * lane + 2] = h1;
        }
        return;
    }

    // MODE 1: BN+ReLU fp32 fragment stores (gamma/beta hoisted per nt)
    float* outB = Out + bz * oBS;
    #pragma unroll
    for (int nt = 0; nt < 8; ++nt) {
        const int c0 = blockIdx.x * 128 + wn * 64 + nt * 8 + (lane & 3) * 2;
        const float s0 = __ldg(&gamma[c0])     * inv;
        const float s1 = __ldg(&gamma[c0 + 1]) * inv;
        const float b0 = __ldg(&beta[c0]);
        const float b1 = __ldg(&beta[c0 + 1]);
        #pragma unroll
        for (int mi = 0; mi < 2; ++mi) {
            const int r0 = blockIdx.y * 128 + wm * 32 + mi * 16 + (lane >> 2);
            float v0 = fmaxf(fmaf(acc[mi][nt][0], s0, b0), 0.0f);
            float v1 = fmaxf(fmaf(acc[mi][nt][1], s1, b1), 0.0f);
            float v2 = fmaxf(fmaf(acc[mi][nt][2], s0, b0), 0.0f);
            float v3 = fmaxf(fmaf(acc[mi][nt][3], s1, b1), 0.0f);
            outB[(size_t)c0       * outLd + r0]     = v0;
            outB[(size_t)(c0 + 1) * outLd + r0]     = v1;
            outB[(size_t)c0       * outLd + r0 + 8] = v2;
            outB[(size_t)(c0 + 1) * outLd + r0 + 8] = v3;
        }
    }
}

// ---------------------------------------------------------------------------
extern "C" void kernel_launch(void* const* d_in, const int* in_sizes, int n_in,
                              void* d_out, int out_size)
{
    const float* xyz1   = (const float*)d_in[0];
    const float* xyz2   = (const float*)d_in[1];
    const float* feat1  = (const float*)d_in[2];
    const float* feat2  = (const float*)d_in[3];
    const float* w1     = (const float*)d_in[4];
    const float* gamma1 = (const float*)d_in[5];
    const float* beta1  = (const float*)d_in[6];
    const float* w2     = (const float*)d_in[7];
    const float* gamma2 = (const float*)d_in[8];
    const float* beta2  = (const float*)d_in[9];
    float* out = (float*)d_out;

    __half *X1f, *X2f, *Hf, *W1af, *W1bf, *W2f;
    cudaGetSymbolAddress((void**)&X1f,  g_X1f);
    cudaGetSymbolAddress((void**)&X2f,  g_X2f);
    cudaGetSymbolAddress((void**)&Hf,   g_Hf);
    cudaGetSymbolAddress((void**)&W1af, g_W1af);
    cudaGetSymbolAddress((void**)&W1bf, g_W1bf);
    cudaGetSymbolAddress((void**)&W2f,  g_W2f);

    cudaFuncSetAttribute(mma_gemm<0>, cudaFuncAttributeMaxDynamicSharedMemorySize, SMEM_GEMM);
    cudaFuncSetAttribute(mma_gemm<1>, cudaFuncAttributeMaxDynamicSharedMemorySize, SMEM_GEMM);
    cudaFuncSetAttribute(mma_gemm<2>, cudaFuncAttributeMaxDynamicSharedMemorySize, SMEM_GEMM);

    // 1. merged prep: kNN + weight converts + feature transposes
    prep_kernel<<<PREP_TOTAL, 256>>>(xyz1, xyz2, feat1, feat2, w1, w2);

    // 2. G[b][m][o] = W1a @ feat2  -> fp16 g_Gh
    mma_gemm<0><<<dim3(MPTS / 128, CH / 128, BB), 256, SMEM_GEMM>>>(
        W1af, 0, 0, X2f, (size_t)MPTS * CH, 1,
        nullptr, 0, 0, nullptr, nullptr);

    // 3. F GEMM fused with interpolation/BN/ReLU -> g_Hf
    mma_gemm<2><<<dim3(NPTS / 128, CH / 128, BB), 256, SMEM_GEMM>>>(
        W1bf, 0, 0, X1f, (size_t)NPTS * CH, 1,
        nullptr, 0, 0, gamma1, beta1);

    // 4. Out[b][o][n] = relu(bn(W2 @ H))
    mma_gemm<1><<<dim3(CH / 128, NPTS / 128, BB), 256, SMEM_GEMM>>>(
        Hf, (size_t)NPTS * CH, 1, W2f, 0, 0,
        out, (size_t)CH * NPTS, NPTS, gamma2, beta2);

    (void)in_sizes; (void)n_in; (void)out_size;
}